// round 5
// baseline (speedup 1.0000x reference)
#include <cuda_runtime.h>
#include <math.h>

// ---------------------------------------------------------------------------
// Fixed scattering network: 2D Morlet scattering (J=4, L=4, N=128, B=64) + MLP
// R3 change: register-resident 128-pt line FFTs. 16 threads per line hold
// e = s + 16m (m=0..7). Stages h=1,2,4,8 via shfl_xor; h=16,32,64 in-register
// radix-8. All twiddles are per-lane constants. One smem store + one load per
// axis, conflict-free with PITCH=129. 1024 threads/block (32 warps/SM).
// ---------------------------------------------------------------------------

#define NB 64
#define NN 128
#define NPIX (NN*NN)
#define PITCH 129      // float2 pitch
#define PITCHF 129     // float pitch for u buffer
#define NT 1024

__device__ float2 g_Ihat[NB * NPIX];            // bitrev both dims
__device__ float2 g_U1hat[NB * 3 * 4 * NPIX];   // j1 in {0,1,2}
__device__ float  g_psi[16 * NPIX];             // bitrev both dims
__device__ float  g_s0[NB];
__device__ float  g_s1p[NB * 4 * 4];
__device__ float  g_s2p[NB * 6 * 16];

__constant__ int c_j1[6] = {0,0,0,1,1,2};
__constant__ int c_j2[6] = {1,2,3,2,3,3};

#define C_SQH 0.70710678118654752440f

static __device__ __forceinline__ float2 cmul(float2 a, float2 b){ return make_float2(a.x*b.x-a.y*b.y, a.x*b.y+a.y*b.x); }
static __device__ __forceinline__ float2 cconj(float2 a){ return make_float2(a.x, -a.y); }
static __device__ __forceinline__ float2 mul_i(float2 a){ return make_float2(-a.y, a.x); }
static __device__ __forceinline__ float2 mul_negi(float2 a){ return make_float2(a.y, -a.x); }
static __device__ __forceinline__ int brev7(int x){ return (int)(__brev((unsigned)x) >> 25); }

// ---------------------------------------------------------------------------
// Per-lane twiddle constants (s = lane index within 16-thread line team)
// Forward values W^k = e^{-2 pi i k / 128}:
//   w1 = W^s, w2 = W^{2s}, w4 = W^{4s}, c8 = W^{8(s&7)}, c16 = W^{16(s&3)}
// ---------------------------------------------------------------------------
struct LaneTw { float2 w1, w2, w4, c8, c16; int s; };

static __device__ __forceinline__ LaneTw make_tw(int s) {
    LaneTw t; t.s = s;
    float sv, cv;
    sincospif((float)s * (1.f/64.f), &sv, &cv); t.w1  = make_float2(cv, -sv);
    sincospif((float)s * (1.f/32.f), &sv, &cv); t.w2  = make_float2(cv, -sv);
    sincospif((float)s * (1.f/16.f), &sv, &cv); t.w4  = make_float2(cv, -sv);
    sincospif((float)(s&7) * (1.f/8.f), &sv, &cv); t.c8  = make_float2(cv, -sv);
    sincospif((float)(s&3) * (1.f/4.f), &sv, &cv); t.c16 = make_float2(cv, -sv);
    return t;
}

// butterflies -----------------------------------------------------------------
static __device__ __forceinline__ void bf_inv(float2& lo, float2& hi, float2 wc) {
    float tx = hi.x*wc.x - hi.y*wc.y, ty = hi.x*wc.y + hi.y*wc.x;
    hi.x = lo.x - tx; hi.y = lo.y - ty;
    lo.x += tx; lo.y += ty;
}
static __device__ __forceinline__ void bf_fwd(float2& lo, float2& hi, float2 w) {
    float dx = lo.x - hi.x, dy = lo.y - hi.y;
    lo.x += hi.x; lo.y += hi.y;
    hi.x = dx*w.x - dy*w.y; hi.y = dx*w.y + dy*w.x;
}

// cross-thread stages ---------------------------------------------------------
template<int H>
static __device__ __forceinline__ void cross_inv(float2* x, float2 wc, int s) {
    const bool up = (s & H) != 0;
    #pragma unroll
    for (int m = 0; m < 8; ++m) {
        float rx = __shfl_xor_sync(0xffffffffu, x[m].x, H);
        float ry = __shfl_xor_sync(0xffffffffu, x[m].y, H);
        float ax = up ? rx : x[m].x, ay = up ? ry : x[m].y;
        float bx = up ? x[m].x : rx, by = up ? x[m].y : ry;
        float tx = bx*wc.x - by*wc.y, ty = bx*wc.y + by*wc.x;
        x[m].x = up ? ax - tx : ax + tx;
        x[m].y = up ? ay - ty : ay + ty;
    }
}
template<int H>
static __device__ __forceinline__ void cross_fwd(float2* x, float2 w, int s) {
    const bool up = (s & H) != 0;
    #pragma unroll
    for (int m = 0; m < 8; ++m) {
        float rx = __shfl_xor_sync(0xffffffffu, x[m].x, H);
        float ry = __shfl_xor_sync(0xffffffffu, x[m].y, H);
        float ax = up ? rx : x[m].x, ay = up ? ry : x[m].y;
        float bx = up ? x[m].x : rx, by = up ? x[m].y : ry;
        float dx = ax - bx, dy = ay - by;
        float ox = up ? dx*w.x - dy*w.y : ax + bx;
        float oy = up ? dx*w.y + dy*w.x : ay + by;
        x[m].x = ox; x[m].y = oy;
    }
}

// full 128-pt line FFTs (8 elements/thread, 16 threads) -----------------------
// inverse DIT: bitrev-positions in -> natural out, unnormalized (x128)
static __device__ __forceinline__ void fft8_inv(float2* x, const LaneTw& T) {
    const int s = T.s;
    cross_inv<1>(x, make_float2(1.f, 0.f), s);
    float2 wc2 = (s & 1) ? make_float2(0.f, 1.f) : make_float2(1.f, 0.f);
    cross_inv<2>(x, wc2, s);
    cross_inv<4>(x, cconj(T.c16), s);
    cross_inv<8>(x, cconj(T.c8), s);
    float2 w4c = cconj(T.w4), w2c = cconj(T.w2), w1c = cconj(T.w1);
    bf_inv(x[0],x[1],w4c); bf_inv(x[2],x[3],w4c); bf_inv(x[4],x[5],w4c); bf_inv(x[6],x[7],w4c);
    float2 w2ci = mul_i(w2c);
    bf_inv(x[0],x[2],w2c); bf_inv(x[1],x[3],w2ci); bf_inv(x[4],x[6],w2c); bf_inv(x[5],x[7],w2ci);
    float2 u0 = w1c;
    float2 u1 = cmul(w1c, make_float2(C_SQH, C_SQH));
    float2 u2 = mul_i(w1c);
    float2 u3 = cmul(w1c, make_float2(-C_SQH, C_SQH));
    bf_inv(x[0],x[4],u0); bf_inv(x[1],x[5],u1); bf_inv(x[2],x[6],u2); bf_inv(x[3],x[7],u3);
}
// forward DIF: natural in -> bitrev-positions out
static __device__ __forceinline__ void fft8_fwd(float2* x, const LaneTw& T) {
    const int s = T.s;
    float2 v0 = T.w1;
    float2 v1 = cmul(T.w1, make_float2(C_SQH, -C_SQH));
    float2 v2 = mul_negi(T.w1);
    float2 v3 = cmul(T.w1, make_float2(-C_SQH, -C_SQH));
    bf_fwd(x[0],x[4],v0); bf_fwd(x[1],x[5],v1); bf_fwd(x[2],x[6],v2); bf_fwd(x[3],x[7],v3);
    float2 w2n = mul_negi(T.w2);
    bf_fwd(x[0],x[2],T.w2); bf_fwd(x[1],x[3],w2n); bf_fwd(x[4],x[6],T.w2); bf_fwd(x[5],x[7],w2n);
    bf_fwd(x[0],x[1],T.w4); bf_fwd(x[2],x[3],T.w4); bf_fwd(x[4],x[5],T.w4); bf_fwd(x[6],x[7],T.w4);
    cross_fwd<8>(x, T.c8, s);
    cross_fwd<4>(x, T.c16, s);
    float2 wf2 = (s & 1) ? make_float2(0.f, -1.f) : make_float2(1.f, 0.f);
    cross_fwd<2>(x, wf2, s);
    cross_fwd<1>(x, make_float2(1.f, 0.f), s);
}

// deterministic block reduction, 1024 threads = 32 warps ----------------------
static __device__ __forceinline__ float block_reduce32(float v, float* rbuf) {
    #pragma unroll
    for (int o = 16; o > 0; o >>= 1) v += __shfl_down_sync(0xffffffffu, v, o);
    if ((threadIdx.x & 31) == 0) rbuf[threadIdx.x >> 5] = v;
    __syncthreads();
    float sres = 0.f;
    if (threadIdx.x == 0) {
        #pragma unroll
        for (int i = 0; i < 32; ++i) sres += rbuf[i];
    }
    __syncthreads();
    return sres;   // valid on thread 0 only
}

// ---------------------------------------------------------------------------
// K0: PSI in bit-reversed 2D order
// ---------------------------------------------------------------------------
static __device__ __forceinline__ float freqval(int i) {
    return (float)((i < 64) ? i : i - 128) * (6.283185307179586476925287e0f / 128.0f);
}
__global__ void k_psi() {
    int j = blockIdx.x >> 2, l = blockIdx.x & 3;
    float k0  = 2.356194490192345f / (float)(1 << j);
    float sg  = 0.8f * (float)(1 << j);
    float s2  = sg * sg;
    float th  = 0.7853981633974483f * (float)l;
    float k0x = k0 * cosf(th), k0y = k0 * sinf(th);
    float beta = expf(-0.5f * s2 * k0 * k0);
    float* dst = g_psi + (j * 4 + l) * NPIX;
    for (int e = threadIdx.x; e < NPIX; e += blockDim.x) {
        int r = e >> 7, c = e & 127;
        float kx = freqval(brev7(r));
        float ky = freqval(brev7(c));
        float dx = kx - k0x, dy = ky - k0y;
        float g1 = expf(-0.5f * s2 * (dx * dx + dy * dy));
        float g0 = expf(-0.5f * s2 * (kx * kx + ky * ky));
        dst[e] = g1 - beta * g0;
    }
}

// ---------------------------------------------------------------------------
// K1: I_hat = fft2(image) (bitrev out) + s0.  grid = 64
// ---------------------------------------------------------------------------
__global__ __launch_bounds__(NT, 1)
void k_fft_image(const float* __restrict__ img) {
    extern __shared__ char sm[];
    float2* tile = (float2*)sm;
    float*  rbuf = (float*)(tile + NN * PITCH);
    const int tid = threadIdx.x;
    const int s = tid & 15, grp = tid >> 4;
    LaneTw T = make_tw(s);
    const float* src = img + (size_t)blockIdx.x * NPIX;
    float acc = 0.f;
    #pragma unroll
    for (int it = 0; it < 2; ++it) {
        int r = grp + 64 * it;
        float2 x[8];
        #pragma unroll
        for (int m = 0; m < 8; ++m) {
            float v = src[r * NN + s + 16 * m];
            acc += v;
            x[m] = make_float2(v, 0.f);
        }
        fft8_fwd(x, T);
        #pragma unroll
        for (int m = 0; m < 8; ++m) tile[r * PITCH + s + 16 * m] = x[m];
    }
    float tot = block_reduce32(acc, rbuf);   // syncs cover store->load
    if (tid == 0) g_s0[blockIdx.x] = tot * (1.f / 16384.f);
    #pragma unroll
    for (int it = 0; it < 2; ++it) {
        int c = grp + 64 * it;
        float2 x[8];
        #pragma unroll
        for (int m = 0; m < 8; ++m) x[m] = tile[(s + 16 * m) * PITCH + c];
        fft8_fwd(x, T);
        #pragma unroll
        for (int m = 0; m < 8; ++m) tile[(s + 16 * m) * PITCH + c] = x[m];
    }
    __syncthreads();
    float2* dst = g_Ihat + (size_t)blockIdx.x * NPIX;
    for (int e = tid; e < NPIX; e += NT)
        dst[e] = tile[(e >> 7) * PITCH + (e & 127)];
}

// ---------------------------------------------------------------------------
// K2: u1 = |ifft2(I_hat*PSI)|/N^2; s1 partial; u1_hat = fft2(u1) (j<3). grid=1024
// ---------------------------------------------------------------------------
__global__ __launch_bounds__(NT, 1)
void k_first() {
    extern __shared__ char sm[];
    float2* tile = (float2*)sm;
    float*  su   = (float*)(tile + NN * PITCH);   // [128][PITCHF]
    float*  rbuf = su + NN * PITCHF;
    const int tid = threadIdx.x;
    const int s = tid & 15, grp = tid >> 4;
    LaneTw T = make_tw(s);
    int idx = blockIdx.x;
    int b = idx >> 4, j = (idx >> 2) & 3, l = idx & 3;
    const float2* ih = g_Ihat + (size_t)b * NPIX;
    const float*  ps = g_psi + (j * 4 + l) * NPIX;
    // A: row inverse
    #pragma unroll
    for (int it = 0; it < 2; ++it) {
        int r = grp + 64 * it;
        float2 x[8];
        #pragma unroll
        for (int m = 0; m < 8; ++m) {
            int e = r * NN + s + 16 * m;
            float2 v = ih[e];
            float q = ps[e];
            x[m] = make_float2(v.x * q, v.y * q);
        }
        fft8_inv(x, T);
        #pragma unroll
        for (int m = 0; m < 8; ++m) tile[r * PITCH + s + 16 * m] = x[m];
    }
    __syncthreads();
    // B: col inverse -> u, s1 accumulate
    float acc = 0.f;
    #pragma unroll
    for (int it = 0; it < 2; ++it) {
        int c = grp + 64 * it;
        float2 x[8];
        #pragma unroll
        for (int m = 0; m < 8; ++m) x[m] = tile[(s + 16 * m) * PITCH + c];
        fft8_inv(x, T);
        #pragma unroll
        for (int m = 0; m < 8; ++m) {
            float u = sqrtf(x[m].x * x[m].x + x[m].y * x[m].y) * (1.f / 16384.f);
            acc += u;
            su[(s + 16 * m) * PITCHF + c] = u;
        }
    }
    float tot = block_reduce32(acc, rbuf);   // syncs cover su store->load
    if (tid == 0) g_s1p[(b * 4 + j) * 4 + l] = tot;
    if (j < 3) {
        // C: row forward of u
        #pragma unroll
        for (int it = 0; it < 2; ++it) {
            int r = grp + 64 * it;
            float2 x[8];
            #pragma unroll
            for (int m = 0; m < 8; ++m)
                x[m] = make_float2(su[r * PITCHF + s + 16 * m], 0.f);
            fft8_fwd(x, T);
            #pragma unroll
            for (int m = 0; m < 8; ++m) tile[r * PITCH + s + 16 * m] = x[m];
        }
        __syncthreads();
        // D: col forward (in place)
        #pragma unroll
        for (int it = 0; it < 2; ++it) {
            int c = grp + 64 * it;
            float2 x[8];
            #pragma unroll
            for (int m = 0; m < 8; ++m) x[m] = tile[(s + 16 * m) * PITCH + c];
            fft8_fwd(x, T);
            #pragma unroll
            for (int m = 0; m < 8; ++m) tile[(s + 16 * m) * PITCH + c] = x[m];
        }
        __syncthreads();
        float2* dst = g_U1hat + ((size_t)(b * 3 + j) * 4 + l) * NPIX;
        for (int e = tid; e < NPIX; e += NT)
            dst[e] = tile[(e >> 7) * PITCH + (e & 127)];
    }
}

// ---------------------------------------------------------------------------
// K3: s2 partial = sum |ifft2(u1_hat * PSI_{j2,l2})|.  grid = 6144
// ---------------------------------------------------------------------------
__global__ __launch_bounds__(NT, 1)
void k_second() {
    extern __shared__ char sm[];
    float2* tile = (float2*)sm;
    float*  rbuf = (float*)(tile + NN * PITCH);
    const int tid = threadIdx.x;
    const int s = tid & 15, grp = tid >> 4;
    LaneTw T = make_tw(s);
    int idx = blockIdx.x;
    int b = idx / 96;
    int r0 = idx - b * 96;
    int p = r0 >> 4, l1 = (r0 >> 2) & 3, l2 = r0 & 3;
    int j1 = c_j1[p], j2 = c_j2[p];
    const float2* uh = g_U1hat + ((size_t)(b * 3 + j1) * 4 + l1) * NPIX;
    const float*  ps = g_psi + (j2 * 4 + l2) * NPIX;
    // A: row inverse (load+multiply fused into registers)
    #pragma unroll
    for (int it = 0; it < 2; ++it) {
        int r = grp + 64 * it;
        float2 x[8];
        #pragma unroll
        for (int m = 0; m < 8; ++m) {
            int e = r * NN + s + 16 * m;
            float2 v = uh[e];
            float q = ps[e];
            x[m] = make_float2(v.x * q, v.y * q);
        }
        fft8_inv(x, T);
        #pragma unroll
        for (int m = 0; m < 8; ++m) tile[r * PITCH + s + 16 * m] = x[m];
    }
    __syncthreads();
    // B: col inverse + |.| accumulate from registers
    float acc = 0.f;
    #pragma unroll
    for (int it = 0; it < 2; ++it) {
        int c = grp + 64 * it;
        float2 x[8];
        #pragma unroll
        for (int m = 0; m < 8; ++m) x[m] = tile[(s + 16 * m) * PITCH + c];
        fft8_inv(x, T);
        #pragma unroll
        for (int m = 0; m < 8; ++m)
            acc += sqrtf(x[m].x * x[m].x + x[m].y * x[m].y);
    }
    float tot = block_reduce32(acc, rbuf);
    if (tid == 0) g_s2p[(b * 6 + p) * 16 + (l1 * 4 + l2)] = tot * (1.f / 16384.f);
}

// ---------------------------------------------------------------------------
// K4: finalize + MLP
// ---------------------------------------------------------------------------
__global__ void k_final(const float* __restrict__ fc1w, const float* __restrict__ fc1b,
                        const float* __restrict__ fc2w, const float* __restrict__ fc2b,
                        float* __restrict__ out) {
    int b = threadIdx.x;
    if (b >= NB) return;
    float coeffs[11];
    coeffs[0] = g_s0[b];
    #pragma unroll
    for (int j = 0; j < 4; ++j) {
        float s = 0.f;
        #pragma unroll
        for (int l = 0; l < 4; ++l) s += g_s1p[(b * 4 + j) * 4 + l];
        coeffs[1 + j] = s * (1.f / 65536.f);
    }
    #pragma unroll
    for (int p = 0; p < 6; ++p) {
        float s = 0.f;
        #pragma unroll
        for (int i = 0; i < 16; ++i) s += g_s2p[(b * 6 + p) * 16 + i];
        coeffs[5 + p] = s * (1.f / (16.f * 16384.f));
    }
    float h[4];
    #pragma unroll
    for (int i = 0; i < 4; ++i) {
        float a = fc1b[i];
        #pragma unroll
        for (int k = 0; k < 11; ++k) a += coeffs[k] * fc1w[i * 11 + k];
        h[i] = fmaxf(a, 0.f);
    }
    #pragma unroll
    for (int o = 0; o < 10; ++o) {
        float a = fc2b[o];
        #pragma unroll
        for (int i = 0; i < 4; ++i) a += h[i] * fc2w[o * 4 + i];
        out[b * 10 + o] = 1.f / (1.f + expf(-a));
    }
}

// ---------------------------------------------------------------------------
extern "C" void kernel_launch(void* const* d_in, const int* in_sizes, int n_in,
                              void* d_out, int out_size) {
    (void)in_sizes; (void)n_in; (void)out_size;
    const float* img  = (const float*)d_in[0];
    const float* fc1w = (const float*)d_in[1];
    const float* fc1b = (const float*)d_in[2];
    const float* fc2w = (const float*)d_in[3];
    const float* fc2b = (const float*)d_in[4];
    float* out = (float*)d_out;

    const int smem_tile = NN * PITCH * (int)sizeof(float2) + 64 * (int)sizeof(float);
    const int smem_first = NN * PITCH * (int)sizeof(float2)
                         + NN * PITCHF * (int)sizeof(float) + 64 * (int)sizeof(float);
    cudaFuncSetAttribute(k_fft_image, cudaFuncAttributeMaxDynamicSharedMemorySize, smem_tile);
    cudaFuncSetAttribute(k_first,     cudaFuncAttributeMaxDynamicSharedMemorySize, smem_first);
    cudaFuncSetAttribute(k_second,    cudaFuncAttributeMaxDynamicSharedMemorySize, smem_tile);

    k_psi<<<16, 256>>>();
    k_fft_image<<<NB, NT, smem_tile>>>(img);
    k_first<<<NB * 16, NT, smem_first>>>();
    k_second<<<NB * 96, NT, smem_tile>>>();
    k_final<<<1, 64>>>(fc1w, fc1b, fc2w, fc2b, out);
}

// round 6
// speedup vs baseline: 1.0879x; 1.0879x over previous
#include <cuda_runtime.h>
#include <math.h>

// ---------------------------------------------------------------------------
// Fixed scattering network: 2D Morlet scattering (J=4, L=4, N=128, B=64) + MLP
// R5: R2 smem radix-8/16 structure at 1024 threads (2x occupancy), with
// gmem-fused boundary passes: inverse r16-row reads the spectral product
// straight from gmem; forward r16-col writes straight to gmem (coalesced).
// PSI precomputed in bit-reversed 2D order; DIF fwd / DIT inv, no reorders.
// ---------------------------------------------------------------------------

#define NB 64
#define NN 128
#define NPIX (NN*NN)
#define PITCH 129      // float2 pitch (odd -> conflict-free for row AND col)
#define NT 1024

__device__ float2 g_Ihat[NB * NPIX];            // bitrev both dims
__device__ float2 g_U1hat[NB * 3 * 4 * NPIX];   // j1 in {0,1,2}
__device__ float  g_psi[16 * NPIX];             // bitrev both dims
__device__ float  g_s0[NB];
__device__ float  g_s1p[NB * 4 * 4];
__device__ float  g_s2p[NB * 6 * 16];

__constant__ int c_j1[6] = {0,0,0,1,1,2};
__constant__ int c_j2[6] = {1,2,3,2,3,3};

#define C_SQH 0.70710678118654752440f
#define C_S1 0.92387953251128675613f  // cos(pi/8)
#define C_S3 0.38268343236508977173f  // sin(pi/8)

static __device__ __forceinline__ float2 cadd(float2 a, float2 b){ return make_float2(a.x+b.x, a.y+b.y); }
static __device__ __forceinline__ float2 csub(float2 a, float2 b){ return make_float2(a.x-b.x, a.y-b.y); }
static __device__ __forceinline__ float2 cmul(float2 a, float2 b){ return make_float2(a.x*b.x-a.y*b.y, a.x*b.y+a.y*b.x); }
static __device__ __forceinline__ float2 cconj(float2 a){ return make_float2(a.x, -a.y); }
static __device__ __forceinline__ float2 mul_i(float2 a){ return make_float2(-a.y, a.x); }
static __device__ __forceinline__ float2 mul_negi(float2 a){ return make_float2(a.y, -a.x); }
static __device__ __forceinline__ int brev7(int x){ return (int)(__brev((unsigned)x) >> 25); }

// ---------------------------------------------------------------------------
struct Smem {
    float2* tile;  // [128][PITCH]
    float2* tw;    // [64] W_128^k
    float*  rbuf;  // [32]
};
static __device__ __forceinline__ Smem get_smem() {
    extern __shared__ char sm[];
    Smem s;
    s.tile = (float2*)sm;
    s.tw   = s.tile + NN * PITCH;
    s.rbuf = (float*)(s.tw + 64);
    return s;
}
static __device__ __forceinline__ void init_tw(float2* tw) {
    if (threadIdx.x < 64) {
        float sv, cv;
        sincospif((float)threadIdx.x / 64.0f, &sv, &cv);
        tw[threadIdx.x] = make_float2(cv, -sv);
    }
}
// deterministic reduction (32 warps); result valid on thread 0
static __device__ __forceinline__ float block_reduce32(float v, float* rbuf) {
    #pragma unroll
    for (int o = 16; o > 0; o >>= 1) v += __shfl_down_sync(0xffffffffu, v, o);
    if ((threadIdx.x & 31) == 0) rbuf[threadIdx.x >> 5] = v;
    __syncthreads();
    float sres = 0.f;
    if (threadIdx.x == 0) {
        #pragma unroll
        for (int i = 0; i < 32; ++i) sres += rbuf[i];
    }
    __syncthreads();
    return sres;
}

// ---------------------------------------------------------------------------
// radix-16 butterfly cores on 16 consecutive elements (registers)
// fwd: DIF halves {8,4,2,1}; inv: DIT halves {1,2,4,8}. Constant twiddles.
// ---------------------------------------------------------------------------
static __device__ __forceinline__ void r16_core_fwd(float2* x) {
    const float2 W8[8] = {{1.f,0.f},{C_S1,-C_S3},{C_SQH,-C_SQH},{C_S3,-C_S1},
                          {0.f,-1.f},{-C_S3,-C_S1},{-C_SQH,-C_SQH},{-C_S1,-C_S3}};
    const float2 W16[4] = {{1.f,0.f},{C_SQH,-C_SQH},{0.f,-1.f},{-C_SQH,-C_SQH}};
    float2 a, b;
    #pragma unroll
    for (int j = 0; j < 8; ++j) {
        a=x[j]; b=x[j+8]; x[j]=cadd(a,b); x[j+8]=cmul(csub(a,b), W8[j]);
    }
    #pragma unroll
    for (int h = 0; h < 16; h += 8)
        #pragma unroll
        for (int j = 0; j < 4; ++j) {
            a=x[h+j]; b=x[h+j+4]; x[h+j]=cadd(a,b); x[h+j+4]=cmul(csub(a,b), W16[j]);
        }
    #pragma unroll
    for (int h = 0; h < 16; h += 4) {
        a=x[h];   b=x[h+2]; x[h]  =cadd(a,b); x[h+2]=csub(a,b);
        a=x[h+1]; b=x[h+3]; x[h+1]=cadd(a,b); x[h+3]=mul_negi(csub(a,b));
    }
    #pragma unroll
    for (int h = 0; h < 16; h += 2) {
        a=x[h]; b=x[h+1]; x[h]=cadd(a,b); x[h+1]=csub(a,b);
    }
}
static __device__ __forceinline__ void r16_core_inv(float2* x) {
    const float2 W16c[4] = {{1.f,0.f},{C_SQH,C_SQH},{0.f,1.f},{-C_SQH,C_SQH}};
    const float2 W8c[8]  = {{1.f,0.f},{C_S1,C_S3},{C_SQH,C_SQH},{C_S3,C_S1},
                            {0.f,1.f},{-C_S3,C_S1},{-C_SQH,C_SQH},{-C_S1,C_S3}};
    float2 a, bw;
    #pragma unroll
    for (int h = 0; h < 16; h += 2) {
        a=x[h]; bw=x[h+1]; x[h]=cadd(a,bw); x[h+1]=csub(a,bw);
    }
    #pragma unroll
    for (int h = 0; h < 16; h += 4) {
        a=x[h];   bw=x[h+2];        x[h]  =cadd(a,bw);  x[h+2]=csub(a,bw);
        a=x[h+1]; bw=mul_i(x[h+3]); x[h+1]=cadd(a,bw);  x[h+3]=csub(a,bw);
    }
    #pragma unroll
    for (int h = 0; h < 16; h += 8)
        #pragma unroll
        for (int j = 0; j < 4; ++j) {
            a=x[h+j]; bw=cmul(x[h+j+4], W16c[j]);
            x[h+j]=cadd(a,bw); x[h+j+4]=csub(a,bw);
        }
    #pragma unroll
    for (int j = 0; j < 8; ++j) {
        a=x[j]; bw=cmul(x[j+8], W8c[j]);
        x[j]=cadd(a,bw); x[j+8]=csub(a,bw);
    }
}

// ---------------------------------------------------------------------------
// radix-8 pass (smem<->smem): DIF halves {64,32,16} / DIT halves {16,32,64}
// elements e = off + 16*j over transform index t; lanes carry t (conflict-free)
// ---------------------------------------------------------------------------
template<bool ROW>
static __device__ __forceinline__ int taddr(int e, int t) {
    return ROW ? (t * PITCH + e) : (e * PITCH + t);
}

template<bool ROW>
static __device__ void pass_r8_fwd(float2* tile, const float2* tw) {
    #pragma unroll
    for (int k = 0; k < 2; ++k) {
        int q = threadIdx.x + k * NT;
        int t = q & 127, off = q >> 7;
        int base = ROW ? t * PITCH + off : off * PITCH + t;
        int str  = ROW ? 16 : 16 * PITCH;
        float2 x[8];
        #pragma unroll
        for (int j = 0; j < 8; ++j) x[j] = tile[base + j * str];
        float2 w1 = tw[off], w2 = tw[2*off], w4 = tw[4*off];
        float2 w1c1 = cmul(w1, make_float2(C_SQH, -C_SQH));
        float2 w1c2 = mul_negi(w1);
        float2 w1c3 = cmul(w1, make_float2(-C_SQH, -C_SQH));
        float2 a, b;
        a=x[0]; b=x[4]; x[0]=cadd(a,b); x[4]=cmul(csub(a,b), w1);
        a=x[1]; b=x[5]; x[1]=cadd(a,b); x[5]=cmul(csub(a,b), w1c1);
        a=x[2]; b=x[6]; x[2]=cadd(a,b); x[6]=cmul(csub(a,b), w1c2);
        a=x[3]; b=x[7]; x[3]=cadd(a,b); x[7]=cmul(csub(a,b), w1c3);
        float2 w2n = mul_negi(w2);
        a=x[0]; b=x[2]; x[0]=cadd(a,b); x[2]=cmul(csub(a,b), w2);
        a=x[1]; b=x[3]; x[1]=cadd(a,b); x[3]=cmul(csub(a,b), w2n);
        a=x[4]; b=x[6]; x[4]=cadd(a,b); x[6]=cmul(csub(a,b), w2);
        a=x[5]; b=x[7]; x[5]=cadd(a,b); x[7]=cmul(csub(a,b), w2n);
        #pragma unroll
        for (int p = 0; p < 4; ++p) {
            a=x[2*p]; b=x[2*p+1];
            x[2*p]=cadd(a,b); x[2*p+1]=cmul(csub(a,b), w4);
        }
        #pragma unroll
        for (int j = 0; j < 8; ++j) tile[base + j * str] = x[j];
    }
}

// EPI: 0 store complex; 1 accumulate |y| only; 2 store (|y|*scale,0) + accumulate
template<bool ROW, int EPI>
static __device__ float pass_r8_inv(float2* tile, const float2* tw, float scale) {
    float acc = 0.f;
    #pragma unroll
    for (int k = 0; k < 2; ++k) {
        int q = threadIdx.x + k * NT;
        int t = q & 127, off = q >> 7;
        int base = ROW ? t * PITCH + off : off * PITCH + t;
        int str  = ROW ? 16 : 16 * PITCH;
        float2 x[8];
        #pragma unroll
        for (int j = 0; j < 8; ++j) x[j] = tile[base + j * str];
        float2 w1c = cconj(tw[off]), w2c = cconj(tw[2*off]), w4c = cconj(tw[4*off]);
        float2 a, bw;
        #pragma unroll
        for (int p = 0; p < 4; ++p) {
            a=x[2*p]; bw=cmul(x[2*p+1], w4c);
            x[2*p]=cadd(a,bw); x[2*p+1]=csub(a,bw);
        }
        float2 w2ci = mul_i(w2c);
        a=x[0]; bw=cmul(x[2], w2c ); x[0]=cadd(a,bw); x[2]=csub(a,bw);
        a=x[1]; bw=cmul(x[3], w2ci); x[1]=cadd(a,bw); x[3]=csub(a,bw);
        a=x[4]; bw=cmul(x[6], w2c ); x[4]=cadd(a,bw); x[6]=csub(a,bw);
        a=x[5]; bw=cmul(x[7], w2ci); x[5]=cadd(a,bw); x[7]=csub(a,bw);
        float2 u0 = w1c;
        float2 u1 = cmul(w1c, make_float2(C_SQH, C_SQH));
        float2 u2 = mul_i(w1c);
        float2 u3 = cmul(w1c, make_float2(-C_SQH, C_SQH));
        a=x[0]; bw=cmul(x[4], u0); x[0]=cadd(a,bw); x[4]=csub(a,bw);
        a=x[1]; bw=cmul(x[5], u1); x[1]=cadd(a,bw); x[5]=csub(a,bw);
        a=x[2]; bw=cmul(x[6], u2); x[2]=cadd(a,bw); x[6]=csub(a,bw);
        a=x[3]; bw=cmul(x[7], u3); x[3]=cadd(a,bw); x[7]=csub(a,bw);
        if (EPI == 0) {
            #pragma unroll
            for (int j = 0; j < 8; ++j) tile[base + j * str] = x[j];
        } else {
            #pragma unroll
            for (int j = 0; j < 8; ++j) {
                float m = sqrtf(x[j].x * x[j].x + x[j].y * x[j].y);
                if (EPI == 2) {
                    m *= scale;
                    tile[base + j * str] = make_float2(m, 0.f);
                }
                acc += m;
            }
        }
    }
    return acc;
}

// ---------------------------------------------------------------------------
// r16 boundary passes
// ---------------------------------------------------------------------------
// inverse entry: read spectral product straight from gmem (float4 vectorized),
// run r16 row core, store into smem tile.  1024 items = 128 rows x 8 groups.
static __device__ void r16_row_inv_from_gmem(float2* tile,
                                             const float2* __restrict__ uh,
                                             const float* __restrict__ ps) {
    int q = threadIdx.x;
    int t = q & 127, g = q >> 7;
    const float4* u4 = (const float4*)(uh + t * NN + 16 * g);
    const float4* p4 = (const float4*)(ps + t * NN + 16 * g);
    float2 x[16];
    #pragma unroll
    for (int k = 0; k < 4; ++k) {
        float4 p = p4[k];
        float4 a = u4[2*k], b = u4[2*k+1];
        x[4*k+0] = make_float2(a.x * p.x, a.y * p.x);
        x[4*k+1] = make_float2(a.z * p.y, a.w * p.y);
        x[4*k+2] = make_float2(b.x * p.z, b.y * p.z);
        x[4*k+3] = make_float2(b.z * p.w, b.w * p.w);
    }
    r16_core_inv(x);
    int base = t * PITCH + 16 * g;
    #pragma unroll
    for (int j = 0; j < 16; ++j) tile[base + j] = x[j];
}
// inverse col pass, smem in place
static __device__ void r16_col_inv(float2* tile) {
    int q = threadIdx.x;
    int t = q & 127, g = q >> 7;
    int base = (16 * g) * PITCH + t;
    float2 x[16];
    #pragma unroll
    for (int j = 0; j < 16; ++j) x[j] = tile[base + j * PITCH];
    r16_core_inv(x);
    #pragma unroll
    for (int j = 0; j < 16; ++j) tile[base + j * PITCH] = x[j];
}
// forward row pass, smem in place
static __device__ void r16_row_fwd(float2* tile) {
    int q = threadIdx.x;
    int t = q & 127, g = q >> 7;
    int base = t * PITCH + 16 * g;
    float2 x[16];
    #pragma unroll
    for (int j = 0; j < 16; ++j) x[j] = tile[base + j];
    r16_core_fwd(x);
    #pragma unroll
    for (int j = 0; j < 16; ++j) tile[base + j] = x[j];
}
// forward exit: r16 col core, write straight to gmem (lanes -> consecutive t,
// 256B coalesced stores)
static __device__ void r16_col_fwd_to_gmem(float2* tile, float2* __restrict__ dst) {
    int q = threadIdx.x;
    int t = q & 127, g = q >> 7;
    int base = (16 * g) * PITCH + t;
    float2 x[16];
    #pragma unroll
    for (int j = 0; j < 16; ++j) x[j] = tile[base + j * PITCH];
    r16_core_fwd(x);
    #pragma unroll
    for (int j = 0; j < 16; ++j) dst[(16 * g + j) * NN + t] = x[j];
}

// ---------------------------------------------------------------------------
// K0: PSI in bit-reversed 2D order
// ---------------------------------------------------------------------------
static __device__ __forceinline__ float freqval(int i) {
    return (float)((i < 64) ? i : i - 128) * (6.283185307179586476925287e0f / 128.0f);
}
__global__ void k_psi() {
    int j = blockIdx.x >> 2, l = blockIdx.x & 3;
    float k0  = 2.356194490192345f / (float)(1 << j);
    float sg  = 0.8f * (float)(1 << j);
    float s2  = sg * sg;
    float th  = 0.7853981633974483f * (float)l;
    float k0x = k0 * cosf(th), k0y = k0 * sinf(th);
    float beta = expf(-0.5f * s2 * k0 * k0);
    float* dst = g_psi + (j * 4 + l) * NPIX;
    for (int e = threadIdx.x; e < NPIX; e += blockDim.x) {
        int r = e >> 7, c = e & 127;
        float kx = freqval(brev7(r));
        float ky = freqval(brev7(c));
        float dx = kx - k0x, dy = ky - k0y;
        float g1 = expf(-0.5f * s2 * (dx * dx + dy * dy));
        float g0 = expf(-0.5f * s2 * (kx * kx + ky * ky));
        dst[e] = g1 - beta * g0;
    }
}

// ---------------------------------------------------------------------------
// K1: I_hat = fft2(image) + s0.  grid = 64
// ---------------------------------------------------------------------------
__global__ __launch_bounds__(NT, 1)
void k_fft_image(const float* __restrict__ img) {
    Smem s = get_smem();
    init_tw(s.tw);
    const float* src = img + (size_t)blockIdx.x * NPIX;
    float acc = 0.f;
    for (int e = threadIdx.x; e < NPIX; e += NT) {
        float v = src[e];
        acc += v;
        s.tile[(e >> 7) * PITCH + (e & 127)] = make_float2(v, 0.f);
    }
    float tot = block_reduce32(acc, s.rbuf);   // syncs cover store->use
    if (threadIdx.x == 0) g_s0[blockIdx.x] = tot * (1.f / 16384.f);
    pass_r8_fwd<true>(s.tile, s.tw); __syncthreads();
    r16_row_fwd(s.tile);             __syncthreads();
    pass_r8_fwd<false>(s.tile, s.tw); __syncthreads();
    r16_col_fwd_to_gmem(s.tile, g_Ihat + (size_t)blockIdx.x * NPIX);
}

// ---------------------------------------------------------------------------
// K2: u1 = |ifft2(I_hat*PSI)|/N^2; s1; u1_hat = fft2(u1) (j<3).  grid = 1024
// ---------------------------------------------------------------------------
__global__ __launch_bounds__(NT, 1)
void k_first() {
    Smem s = get_smem();
    init_tw(s.tw);
    int idx = blockIdx.x;
    int b = idx >> 4, j = (idx >> 2) & 3, l = idx & 3;
    const float2* ih = g_Ihat + (size_t)b * NPIX;
    const float*  ps = g_psi + (j * 4 + l) * NPIX;
    // inverse 2D
    r16_row_inv_from_gmem(s.tile, ih, ps);      __syncthreads();
    pass_r8_inv<true, 0>(s.tile, s.tw, 0.f);    __syncthreads();
    r16_col_inv(s.tile);                        __syncthreads();
    float acc = pass_r8_inv<false, 2>(s.tile, s.tw, 1.f / 16384.f);
    float tot = block_reduce32(acc, s.rbuf);    // syncs cover (u,0) stores
    if (threadIdx.x == 0) g_s1p[(b * 4 + j) * 4 + l] = tot;
    if (j < 3) {
        pass_r8_fwd<true>(s.tile, s.tw);  __syncthreads();
        r16_row_fwd(s.tile);              __syncthreads();
        pass_r8_fwd<false>(s.tile, s.tw); __syncthreads();
        r16_col_fwd_to_gmem(s.tile, g_U1hat + ((size_t)(b * 3 + j) * 4 + l) * NPIX);
    }
}

// ---------------------------------------------------------------------------
// K3: s2 partial = sum |ifft2(u1_hat * PSI_{j2,l2})|.  grid = 6144
// ---------------------------------------------------------------------------
__global__ __launch_bounds__(NT, 1)
void k_second() {
    Smem s = get_smem();
    init_tw(s.tw);
    int idx = blockIdx.x;
    int b = idx / 96;
    int r0 = idx - b * 96;
    int p = r0 >> 4, l1 = (r0 >> 2) & 3, l2 = r0 & 3;
    int j1 = c_j1[p], j2 = c_j2[p];
    const float2* uh = g_U1hat + ((size_t)(b * 3 + j1) * 4 + l1) * NPIX;
    const float*  ps = g_psi + (j2 * 4 + l2) * NPIX;
    r16_row_inv_from_gmem(s.tile, uh, ps);      __syncthreads();
    pass_r8_inv<true, 0>(s.tile, s.tw, 0.f);    __syncthreads();
    r16_col_inv(s.tile);                        __syncthreads();
    float acc = pass_r8_inv<false, 1>(s.tile, s.tw, 0.f);
    float tot = block_reduce32(acc, s.rbuf);
    if (threadIdx.x == 0) g_s2p[(b * 6 + p) * 16 + (l1 * 4 + l2)] = tot * (1.f / 16384.f);
}

// ---------------------------------------------------------------------------
// K4: finalize + MLP
// ---------------------------------------------------------------------------
__global__ void k_final(const float* __restrict__ fc1w, const float* __restrict__ fc1b,
                        const float* __restrict__ fc2w, const float* __restrict__ fc2b,
                        float* __restrict__ out) {
    int b = threadIdx.x;
    if (b >= NB) return;
    float coeffs[11];
    coeffs[0] = g_s0[b];
    #pragma unroll
    for (int j = 0; j < 4; ++j) {
        float s = 0.f;
        #pragma unroll
        for (int l = 0; l < 4; ++l) s += g_s1p[(b * 4 + j) * 4 + l];
        coeffs[1 + j] = s * (1.f / 65536.f);
    }
    #pragma unroll
    for (int p = 0; p < 6; ++p) {
        float s = 0.f;
        #pragma unroll
        for (int i = 0; i < 16; ++i) s += g_s2p[(b * 6 + p) * 16 + i];
        coeffs[5 + p] = s * (1.f / (16.f * 16384.f));
    }
    float h[4];
    #pragma unroll
    for (int i = 0; i < 4; ++i) {
        float a = fc1b[i];
        #pragma unroll
        for (int k = 0; k < 11; ++k) a += coeffs[k] * fc1w[i * 11 + k];
        h[i] = fmaxf(a, 0.f);
    }
    #pragma unroll
    for (int o = 0; o < 10; ++o) {
        float a = fc2b[o];
        #pragma unroll
        for (int i = 0; i < 4; ++i) a += h[i] * fc2w[o * 4 + i];
        out[b * 10 + o] = 1.f / (1.f + expf(-a));
    }
}

// ---------------------------------------------------------------------------
extern "C" void kernel_launch(void* const* d_in, const int* in_sizes, int n_in,
                              void* d_out, int out_size) {
    (void)in_sizes; (void)n_in; (void)out_size;
    const float* img  = (const float*)d_in[0];
    const float* fc1w = (const float*)d_in[1];
    const float* fc1b = (const float*)d_in[2];
    const float* fc2w = (const float*)d_in[3];
    const float* fc2b = (const float*)d_in[4];
    float* out = (float*)d_out;

    const int smem_sz = NN * PITCH * (int)sizeof(float2)
                      + 64 * (int)sizeof(float2) + 32 * (int)sizeof(float);
    cudaFuncSetAttribute(k_fft_image, cudaFuncAttributeMaxDynamicSharedMemorySize, smem_sz);
    cudaFuncSetAttribute(k_first,     cudaFuncAttributeMaxDynamicSharedMemorySize, smem_sz);
    cudaFuncSetAttribute(k_second,    cudaFuncAttributeMaxDynamicSharedMemorySize, smem_sz);

    k_psi<<<16, 256>>>();
    k_fft_image<<<NB, NT, smem_sz>>>(img);
    k_first<<<NB * 16, NT, smem_sz>>>();
    k_second<<<NB * 96, NT, smem_sz>>>();
    k_final<<<1, 64>>>(fc1w, fc1b, fc2w, fc2b, out);
}

// round 7
// speedup vs baseline: 1.5573x; 1.4315x over previous
#include <cuda_runtime.h>
#include <math.h>

// ---------------------------------------------------------------------------
// Fixed scattering network: 2D Morlet scattering (J=4, L=4, N=128, B=64) + MLP
// R6: R2's smem radix-8/16 structure (coalesced staged entry) at 1024 threads,
// plus the coalesced forward-exit gmem fusion from R5. PSI precomputed in
// bit-reversed 2D order; DIF forward / DIT inverse, no reorder passes.
// ---------------------------------------------------------------------------

#define NB 64
#define NN 128
#define NPIX (NN*NN)
#define PITCH 129      // float2 pitch (odd -> conflict-free row AND col)
#define NT 1024

__device__ float2 g_Ihat[NB * NPIX];            // bitrev both dims
__device__ float2 g_U1hat[NB * 3 * 4 * NPIX];   // j1 in {0,1,2}
__device__ float  g_psi[16 * NPIX];             // bitrev both dims
__device__ float  g_s0[NB];
__device__ float  g_s1p[NB * 4 * 4];
__device__ float  g_s2p[NB * 6 * 16];

__constant__ int c_j1[6] = {0,0,0,1,1,2};
__constant__ int c_j2[6] = {1,2,3,2,3,3};

#define C_SQH 0.70710678118654752440f
#define C_S1 0.92387953251128675613f  // cos(pi/8)
#define C_S3 0.38268343236508977173f  // sin(pi/8)

static __device__ __forceinline__ float2 cadd(float2 a, float2 b){ return make_float2(a.x+b.x, a.y+b.y); }
static __device__ __forceinline__ float2 csub(float2 a, float2 b){ return make_float2(a.x-b.x, a.y-b.y); }
static __device__ __forceinline__ float2 cmul(float2 a, float2 b){ return make_float2(a.x*b.x-a.y*b.y, a.x*b.y+a.y*b.x); }
static __device__ __forceinline__ float2 cconj(float2 a){ return make_float2(a.x, -a.y); }
static __device__ __forceinline__ float2 mul_i(float2 a){ return make_float2(-a.y, a.x); }
static __device__ __forceinline__ float2 mul_negi(float2 a){ return make_float2(a.y, -a.x); }
static __device__ __forceinline__ int brev7(int x){ return (int)(__brev((unsigned)x) >> 25); }

// ---------------------------------------------------------------------------
struct Smem {
    float2* tile;  // [128][PITCH]
    float2* tw;    // [64] W_128^k
    float*  rbuf;  // [32]
};
static __device__ __forceinline__ Smem get_smem() {
    extern __shared__ char sm[];
    Smem s;
    s.tile = (float2*)sm;
    s.tw   = s.tile + NN * PITCH;
    s.rbuf = (float*)(s.tw + 64);
    return s;
}
static __device__ __forceinline__ void init_tw(float2* tw) {
    if (threadIdx.x < 64) {
        float sv, cv;
        sincospif((float)threadIdx.x / 64.0f, &sv, &cv);
        tw[threadIdx.x] = make_float2(cv, -sv);
    }
}
// deterministic reduction (32 warps); result valid on thread 0
static __device__ __forceinline__ float block_reduce32(float v, float* rbuf) {
    #pragma unroll
    for (int o = 16; o > 0; o >>= 1) v += __shfl_down_sync(0xffffffffu, v, o);
    if ((threadIdx.x & 31) == 0) rbuf[threadIdx.x >> 5] = v;
    __syncthreads();
    float sres = 0.f;
    if (threadIdx.x == 0) {
        #pragma unroll
        for (int i = 0; i < 32; ++i) sres += rbuf[i];
    }
    __syncthreads();
    return sres;
}

// ---------------------------------------------------------------------------
// radix-16 butterfly cores (16 consecutive elements, constant twiddles)
// ---------------------------------------------------------------------------
static __device__ __forceinline__ void r16_core_fwd(float2* x) {
    const float2 W8[8] = {{1.f,0.f},{C_S1,-C_S3},{C_SQH,-C_SQH},{C_S3,-C_S1},
                          {0.f,-1.f},{-C_S3,-C_S1},{-C_SQH,-C_SQH},{-C_S1,-C_S3}};
    const float2 W16[4] = {{1.f,0.f},{C_SQH,-C_SQH},{0.f,-1.f},{-C_SQH,-C_SQH}};
    float2 a, b;
    #pragma unroll
    for (int j = 0; j < 8; ++j) {
        a=x[j]; b=x[j+8]; x[j]=cadd(a,b); x[j+8]=cmul(csub(a,b), W8[j]);
    }
    #pragma unroll
    for (int h = 0; h < 16; h += 8)
        #pragma unroll
        for (int j = 0; j < 4; ++j) {
            a=x[h+j]; b=x[h+j+4]; x[h+j]=cadd(a,b); x[h+j+4]=cmul(csub(a,b), W16[j]);
        }
    #pragma unroll
    for (int h = 0; h < 16; h += 4) {
        a=x[h];   b=x[h+2]; x[h]  =cadd(a,b); x[h+2]=csub(a,b);
        a=x[h+1]; b=x[h+3]; x[h+1]=cadd(a,b); x[h+3]=mul_negi(csub(a,b));
    }
    #pragma unroll
    for (int h = 0; h < 16; h += 2) {
        a=x[h]; b=x[h+1]; x[h]=cadd(a,b); x[h+1]=csub(a,b);
    }
}
static __device__ __forceinline__ void r16_core_inv(float2* x) {
    const float2 W16c[4] = {{1.f,0.f},{C_SQH,C_SQH},{0.f,1.f},{-C_SQH,C_SQH}};
    const float2 W8c[8]  = {{1.f,0.f},{C_S1,C_S3},{C_SQH,C_SQH},{C_S3,C_S1},
                            {0.f,1.f},{-C_S3,C_S1},{-C_SQH,C_SQH},{-C_S1,C_S3}};
    float2 a, bw;
    #pragma unroll
    for (int h = 0; h < 16; h += 2) {
        a=x[h]; bw=x[h+1]; x[h]=cadd(a,bw); x[h+1]=csub(a,bw);
    }
    #pragma unroll
    for (int h = 0; h < 16; h += 4) {
        a=x[h];   bw=x[h+2];        x[h]  =cadd(a,bw);  x[h+2]=csub(a,bw);
        a=x[h+1]; bw=mul_i(x[h+3]); x[h+1]=cadd(a,bw);  x[h+3]=csub(a,bw);
    }
    #pragma unroll
    for (int h = 0; h < 16; h += 8)
        #pragma unroll
        for (int j = 0; j < 4; ++j) {
            a=x[h+j]; bw=cmul(x[h+j+4], W16c[j]);
            x[h+j]=cadd(a,bw); x[h+j+4]=csub(a,bw);
        }
    #pragma unroll
    for (int j = 0; j < 8; ++j) {
        a=x[j]; bw=cmul(x[j+8], W8c[j]);
        x[j]=cadd(a,bw); x[j+8]=csub(a,bw);
    }
}

// ---------------------------------------------------------------------------
// radix-8 pass (smem<->smem): DIF halves {64,32,16} / DIT halves {16,32,64}
// elements e = off + 16*j; lanes carry transform index t (conflict-free)
// ---------------------------------------------------------------------------
template<bool ROW>
static __device__ void pass_r8_fwd(float2* tile, const float2* tw) {
    #pragma unroll
    for (int k = 0; k < 2; ++k) {
        int q = threadIdx.x + k * NT;
        int t = q & 127, off = q >> 7;
        int base = ROW ? t * PITCH + off : off * PITCH + t;
        int str  = ROW ? 16 : 16 * PITCH;
        float2 x[8];
        #pragma unroll
        for (int j = 0; j < 8; ++j) x[j] = tile[base + j * str];
        float2 w1 = tw[off], w2 = tw[2*off], w4 = tw[4*off];
        float2 w1c1 = cmul(w1, make_float2(C_SQH, -C_SQH));
        float2 w1c2 = mul_negi(w1);
        float2 w1c3 = cmul(w1, make_float2(-C_SQH, -C_SQH));
        float2 a, b;
        a=x[0]; b=x[4]; x[0]=cadd(a,b); x[4]=cmul(csub(a,b), w1);
        a=x[1]; b=x[5]; x[1]=cadd(a,b); x[5]=cmul(csub(a,b), w1c1);
        a=x[2]; b=x[6]; x[2]=cadd(a,b); x[6]=cmul(csub(a,b), w1c2);
        a=x[3]; b=x[7]; x[3]=cadd(a,b); x[7]=cmul(csub(a,b), w1c3);
        float2 w2n = mul_negi(w2);
        a=x[0]; b=x[2]; x[0]=cadd(a,b); x[2]=cmul(csub(a,b), w2);
        a=x[1]; b=x[3]; x[1]=cadd(a,b); x[3]=cmul(csub(a,b), w2n);
        a=x[4]; b=x[6]; x[4]=cadd(a,b); x[6]=cmul(csub(a,b), w2);
        a=x[5]; b=x[7]; x[5]=cadd(a,b); x[7]=cmul(csub(a,b), w2n);
        #pragma unroll
        for (int p = 0; p < 4; ++p) {
            a=x[2*p]; b=x[2*p+1];
            x[2*p]=cadd(a,b); x[2*p+1]=cmul(csub(a,b), w4);
        }
        #pragma unroll
        for (int j = 0; j < 8; ++j) tile[base + j * str] = x[j];
    }
}

// EPI: 0 store complex; 1 accumulate |y| only; 2 store (|y|*scale,0) + accumulate
template<bool ROW, int EPI>
static __device__ float pass_r8_inv(float2* tile, const float2* tw, float scale) {
    float acc = 0.f;
    #pragma unroll
    for (int k = 0; k < 2; ++k) {
        int q = threadIdx.x + k * NT;
        int t = q & 127, off = q >> 7;
        int base = ROW ? t * PITCH + off : off * PITCH + t;
        int str  = ROW ? 16 : 16 * PITCH;
        float2 x[8];
        #pragma unroll
        for (int j = 0; j < 8; ++j) x[j] = tile[base + j * str];
        float2 w1c = cconj(tw[off]), w2c = cconj(tw[2*off]), w4c = cconj(tw[4*off]);
        float2 a, bw;
        #pragma unroll
        for (int p = 0; p < 4; ++p) {
            a=x[2*p]; bw=cmul(x[2*p+1], w4c);
            x[2*p]=cadd(a,bw); x[2*p+1]=csub(a,bw);
        }
        float2 w2ci = mul_i(w2c);
        a=x[0]; bw=cmul(x[2], w2c ); x[0]=cadd(a,bw); x[2]=csub(a,bw);
        a=x[1]; bw=cmul(x[3], w2ci); x[1]=cadd(a,bw); x[3]=csub(a,bw);
        a=x[4]; bw=cmul(x[6], w2c ); x[4]=cadd(a,bw); x[6]=csub(a,bw);
        a=x[5]; bw=cmul(x[7], w2ci); x[5]=cadd(a,bw); x[7]=csub(a,bw);
        float2 u0 = w1c;
        float2 u1 = cmul(w1c, make_float2(C_SQH, C_SQH));
        float2 u2 = mul_i(w1c);
        float2 u3 = cmul(w1c, make_float2(-C_SQH, C_SQH));
        a=x[0]; bw=cmul(x[4], u0); x[0]=cadd(a,bw); x[4]=csub(a,bw);
        a=x[1]; bw=cmul(x[5], u1); x[1]=cadd(a,bw); x[5]=csub(a,bw);
        a=x[2]; bw=cmul(x[6], u2); x[2]=cadd(a,bw); x[6]=csub(a,bw);
        a=x[3]; bw=cmul(x[7], u3); x[3]=cadd(a,bw); x[7]=csub(a,bw);
        if (EPI == 0) {
            #pragma unroll
            for (int j = 0; j < 8; ++j) tile[base + j * str] = x[j];
        } else {
            #pragma unroll
            for (int j = 0; j < 8; ++j) {
                float m = sqrtf(x[j].x * x[j].x + x[j].y * x[j].y);
                if (EPI == 2) {
                    m *= scale;
                    tile[base + j * str] = make_float2(m, 0.f);
                }
                acc += m;
            }
        }
    }
    return acc;
}

// ---------------------------------------------------------------------------
// r16 passes (1024 items = 128 transforms x 8 groups; exactly 1 per thread)
// ---------------------------------------------------------------------------
static __device__ void r16_row_inv(float2* tile) {
    int q = threadIdx.x;
    int t = q & 127, g = q >> 7;
    int base = t * PITCH + 16 * g;
    float2 x[16];
    #pragma unroll
    for (int j = 0; j < 16; ++j) x[j] = tile[base + j];
    r16_core_inv(x);
    #pragma unroll
    for (int j = 0; j < 16; ++j) tile[base + j] = x[j];
}
static __device__ void r16_col_inv(float2* tile) {
    int q = threadIdx.x;
    int t = q & 127, g = q >> 7;
    int base = (16 * g) * PITCH + t;
    float2 x[16];
    #pragma unroll
    for (int j = 0; j < 16; ++j) x[j] = tile[base + j * PITCH];
    r16_core_inv(x);
    #pragma unroll
    for (int j = 0; j < 16; ++j) tile[base + j * PITCH] = x[j];
}
static __device__ void r16_row_fwd(float2* tile) {
    int q = threadIdx.x;
    int t = q & 127, g = q >> 7;
    int base = t * PITCH + 16 * g;
    float2 x[16];
    #pragma unroll
    for (int j = 0; j < 16; ++j) x[j] = tile[base + j];
    r16_core_fwd(x);
    #pragma unroll
    for (int j = 0; j < 16; ++j) tile[base + j] = x[j];
}
// forward exit: r16 col core, coalesced gmem write (lanes -> consecutive t)
static __device__ void r16_col_fwd_to_gmem(float2* tile, float2* __restrict__ dst) {
    int q = threadIdx.x;
    int t = q & 127, g = q >> 7;
    int base = (16 * g) * PITCH + t;
    float2 x[16];
    #pragma unroll
    for (int j = 0; j < 16; ++j) x[j] = tile[base + j * PITCH];
    r16_core_fwd(x);
    #pragma unroll
    for (int j = 0; j < 16; ++j) dst[(16 * g + j) * NN + t] = x[j];
}

// ---------------------------------------------------------------------------
// K0: PSI in bit-reversed 2D order
// ---------------------------------------------------------------------------
static __device__ __forceinline__ float freqval(int i) {
    return (float)((i < 64) ? i : i - 128) * (6.283185307179586476925287e0f / 128.0f);
}
__global__ void k_psi() {
    int j = blockIdx.x >> 2, l = blockIdx.x & 3;
    float k0  = 2.356194490192345f / (float)(1 << j);
    float sg  = 0.8f * (float)(1 << j);
    float s2  = sg * sg;
    float th  = 0.7853981633974483f * (float)l;
    float k0x = k0 * cosf(th), k0y = k0 * sinf(th);
    float beta = expf(-0.5f * s2 * k0 * k0);
    float* dst = g_psi + (j * 4 + l) * NPIX;
    for (int e = threadIdx.x; e < NPIX; e += blockDim.x) {
        int r = e >> 7, c = e & 127;
        float kx = freqval(brev7(r));
        float ky = freqval(brev7(c));
        float dx = kx - k0x, dy = ky - k0y;
        float g1 = expf(-0.5f * s2 * (dx * dx + dy * dy));
        float g0 = expf(-0.5f * s2 * (kx * kx + ky * ky));
        dst[e] = g1 - beta * g0;
    }
}

// ---------------------------------------------------------------------------
// K1: I_hat = fft2(image) + s0.  grid = 64
// ---------------------------------------------------------------------------
__global__ __launch_bounds__(NT, 1)
void k_fft_image(const float* __restrict__ img) {
    Smem s = get_smem();
    init_tw(s.tw);
    const float* src = img + (size_t)blockIdx.x * NPIX;
    float acc = 0.f;
    #pragma unroll
    for (int k = 0; k < NPIX / NT; ++k) {
        int e = threadIdx.x + k * NT;
        float v = src[e];
        acc += v;
        s.tile[(e >> 7) * PITCH + (e & 127)] = make_float2(v, 0.f);
    }
    float tot = block_reduce32(acc, s.rbuf);   // syncs cover store->use
    if (threadIdx.x == 0) g_s0[blockIdx.x] = tot * (1.f / 16384.f);
    pass_r8_fwd<true>(s.tile, s.tw);  __syncthreads();
    r16_row_fwd(s.tile);              __syncthreads();
    pass_r8_fwd<false>(s.tile, s.tw); __syncthreads();
    r16_col_fwd_to_gmem(s.tile, g_Ihat + (size_t)blockIdx.x * NPIX);
}

// ---------------------------------------------------------------------------
// K2: u1 = |ifft2(I_hat*PSI)|/N^2; s1; u1_hat = fft2(u1) (j<3).  grid = 1024
// ---------------------------------------------------------------------------
__global__ __launch_bounds__(NT, 1)
void k_first() {
    Smem s = get_smem();
    init_tw(s.tw);
    int idx = blockIdx.x;
    int b = idx >> 4, j = (idx >> 2) & 3, l = idx & 3;
    const float2* ih = g_Ihat + (size_t)b * NPIX;
    const float*  ps = g_psi + (j * 4 + l) * NPIX;
    // coalesced staged spectral product
    #pragma unroll
    for (int k = 0; k < NPIX / NT; ++k) {
        int e = threadIdx.x + k * NT;
        float2 v = ih[e];
        float q = ps[e];
        s.tile[(e >> 7) * PITCH + (e & 127)] = make_float2(v.x * q, v.y * q);
    }
    __syncthreads();
    r16_row_inv(s.tile);                        __syncthreads();
    pass_r8_inv<true, 0>(s.tile, s.tw, 0.f);    __syncthreads();
    r16_col_inv(s.tile);                        __syncthreads();
    float acc = pass_r8_inv<false, 2>(s.tile, s.tw, 1.f / 16384.f);
    float tot = block_reduce32(acc, s.rbuf);    // syncs cover (u,0) stores
    if (threadIdx.x == 0) g_s1p[(b * 4 + j) * 4 + l] = tot;
    if (j < 3) {
        pass_r8_fwd<true>(s.tile, s.tw);  __syncthreads();
        r16_row_fwd(s.tile);              __syncthreads();
        pass_r8_fwd<false>(s.tile, s.tw); __syncthreads();
        r16_col_fwd_to_gmem(s.tile, g_U1hat + ((size_t)(b * 3 + j) * 4 + l) * NPIX);
    }
}

// ---------------------------------------------------------------------------
// K3: s2 partial = sum |ifft2(u1_hat * PSI_{j2,l2})|.  grid = 6144
// ---------------------------------------------------------------------------
__global__ __launch_bounds__(NT, 1)
void k_second() {
    Smem s = get_smem();
    init_tw(s.tw);
    int idx = blockIdx.x;
    int b = idx / 96;
    int r0 = idx - b * 96;
    int p = r0 >> 4, l1 = (r0 >> 2) & 3, l2 = r0 & 3;
    int j1 = c_j1[p], j2 = c_j2[p];
    const float2* uh = g_U1hat + ((size_t)(b * 3 + j1) * 4 + l1) * NPIX;
    const float*  ps = g_psi + (j2 * 4 + l2) * NPIX;
    #pragma unroll
    for (int k = 0; k < NPIX / NT; ++k) {
        int e = threadIdx.x + k * NT;
        float2 v = uh[e];
        float q = ps[e];
        s.tile[(e >> 7) * PITCH + (e & 127)] = make_float2(v.x * q, v.y * q);
    }
    __syncthreads();
    r16_row_inv(s.tile);                        __syncthreads();
    pass_r8_inv<true, 0>(s.tile, s.tw, 0.f);    __syncthreads();
    r16_col_inv(s.tile);                        __syncthreads();
    float acc = pass_r8_inv<false, 1>(s.tile, s.tw, 0.f);
    float tot = block_reduce32(acc, s.rbuf);
    if (threadIdx.x == 0) g_s2p[(b * 6 + p) * 16 + (l1 * 4 + l2)] = tot * (1.f / 16384.f);
}

// ---------------------------------------------------------------------------
// K4: finalize + MLP
// ---------------------------------------------------------------------------
__global__ void k_final(const float* __restrict__ fc1w, const float* __restrict__ fc1b,
                        const float* __restrict__ fc2w, const float* __restrict__ fc2b,
                        float* __restrict__ out) {
    int b = threadIdx.x;
    if (b >= NB) return;
    float coeffs[11];
    coeffs[0] = g_s0[b];
    #pragma unroll
    for (int j = 0; j < 4; ++j) {
        float s = 0.f;
        #pragma unroll
        for (int l = 0; l < 4; ++l) s += g_s1p[(b * 4 + j) * 4 + l];
        coeffs[1 + j] = s * (1.f / 65536.f);
    }
    #pragma unroll
    for (int p = 0; p < 6; ++p) {
        float s = 0.f;
        #pragma unroll
        for (int i = 0; i < 16; ++i) s += g_s2p[(b * 6 + p) * 16 + i];
        coeffs[5 + p] = s * (1.f / (16.f * 16384.f));
    }
    float h[4];
    #pragma unroll
    for (int i = 0; i < 4; ++i) {
        float a = fc1b[i];
        #pragma unroll
        for (int k = 0; k < 11; ++k) a += coeffs[k] * fc1w[i * 11 + k];
        h[i] = fmaxf(a, 0.f);
    }
    #pragma unroll
    for (int o = 0; o < 10; ++o) {
        float a = fc2b[o];
        #pragma unroll
        for (int i = 0; i < 4; ++i) a += h[i] * fc2w[o * 4 + i];
        out[b * 10 + o] = 1.f / (1.f + expf(-a));
    }
}

// ---------------------------------------------------------------------------
extern "C" void kernel_launch(void* const* d_in, const int* in_sizes, int n_in,
                              void* d_out, int out_size) {
    (void)in_sizes; (void)n_in; (void)out_size;
    const float* img  = (const float*)d_in[0];
    const float* fc1w = (const float*)d_in[1];
    const float* fc1b = (const float*)d_in[2];
    const float* fc2w = (const float*)d_in[3];
    const float* fc2b = (const float*)d_in[4];
    float* out = (float*)d_out;

    const int smem_sz = NN * PITCH * (int)sizeof(float2)
                      + 64 * (int)sizeof(float2) + 32 * (int)sizeof(float);
    cudaFuncSetAttribute(k_fft_image, cudaFuncAttributeMaxDynamicSharedMemorySize, smem_sz);
    cudaFuncSetAttribute(k_first,     cudaFuncAttributeMaxDynamicSharedMemorySize, smem_sz);
    cudaFuncSetAttribute(k_second,    cudaFuncAttributeMaxDynamicSharedMemorySize, smem_sz);

    k_psi<<<16, 256>>>();
    k_fft_image<<<NB, NT, smem_sz>>>(img);
    k_first<<<NB * 16, NT, smem_sz>>>();
    k_second<<<NB * 96, NT, smem_sz>>>();
    k_final<<<1, 64>>>(fc1w, fc1b, fc2w, fc2b, out);
}

// round 9
// speedup vs baseline: 1.6766x; 1.0766x over previous
#include <cuda_runtime.h>
#include <math.h>

// ---------------------------------------------------------------------------
// Fixed scattering network: 2D Morlet scattering (J=4, L=4, N=128, B=64) + MLP
// R7: column-axis-first inverse with the gmem read + PSI product fused into
// the first r16 column pass (coalesced: lanes span consecutive columns).
// Eliminates the staged entry smem round trip in k_first/k_second.
// Forward keeps R6 structure incl. coalesced r16-col exit to gmem.
// ---------------------------------------------------------------------------

#define NB 64
#define NN 128
#define NPIX (NN*NN)
#define PITCH 129      // float2 pitch (odd -> conflict-free row AND col)
#define NT 1024

__device__ float2 g_Ihat[NB * NPIX];            // bitrev both dims
__device__ float2 g_U1hat[NB * 3 * 4 * NPIX];   // j1 in {0,1,2}
__device__ float  g_psi[16 * NPIX];             // bitrev both dims
__device__ float  g_s0[NB];
__device__ float  g_s1p[NB * 4 * 4];
__device__ float  g_s2p[NB * 6 * 16];

__constant__ int c_j1[6] = {0,0,0,1,1,2};
__constant__ int c_j2[6] = {1,2,3,2,3,3};

#define C_SQH 0.70710678118654752440f
#define C_S1 0.92387953251128675613f  // cos(pi/8)
#define C_S3 0.38268343236508977173f  // sin(pi/8)

static __device__ __forceinline__ float2 cadd(float2 a, float2 b){ return make_float2(a.x+b.x, a.y+b.y); }
static __device__ __forceinline__ float2 csub(float2 a, float2 b){ return make_float2(a.x-b.x, a.y-b.y); }
static __device__ __forceinline__ float2 cmul(float2 a, float2 b){ return make_float2(a.x*b.x-a.y*b.y, a.x*b.y+a.y*b.x); }
static __device__ __forceinline__ float2 cconj(float2 a){ return make_float2(a.x, -a.y); }
static __device__ __forceinline__ float2 mul_i(float2 a){ return make_float2(-a.y, a.x); }
static __device__ __forceinline__ float2 mul_negi(float2 a){ return make_float2(a.y, -a.x); }
static __device__ __forceinline__ int brev7(int x){ return (int)(__brev((unsigned)x) >> 25); }

// ---------------------------------------------------------------------------
struct Smem {
    float2* tile;  // [128][PITCH]
    float2* tw;    // [64] W_128^k
    float*  rbuf;  // [32]
};
static __device__ __forceinline__ Smem get_smem() {
    extern __shared__ char sm[];
    Smem s;
    s.tile = (float2*)sm;
    s.tw   = s.tile + NN * PITCH;
    s.rbuf = (float*)(s.tw + 64);
    return s;
}
static __device__ __forceinline__ void init_tw(float2* tw) {
    if (threadIdx.x < 64) {
        float sv, cv;
        sincospif((float)threadIdx.x / 64.0f, &sv, &cv);
        tw[threadIdx.x] = make_float2(cv, -sv);
    }
}
// deterministic reduction (32 warps); result valid on thread 0
static __device__ __forceinline__ float block_reduce32(float v, float* rbuf) {
    #pragma unroll
    for (int o = 16; o > 0; o >>= 1) v += __shfl_down_sync(0xffffffffu, v, o);
    if ((threadIdx.x & 31) == 0) rbuf[threadIdx.x >> 5] = v;
    __syncthreads();
    float sres = 0.f;
    if (threadIdx.x == 0) {
        #pragma unroll
        for (int i = 0; i < 32; ++i) sres += rbuf[i];
    }
    __syncthreads();
    return sres;
}

// ---------------------------------------------------------------------------
// radix-16 butterfly cores (16 consecutive elements, constant twiddles)
// ---------------------------------------------------------------------------
static __device__ __forceinline__ void r16_core_fwd(float2* x) {
    const float2 W8[8] = {{1.f,0.f},{C_S1,-C_S3},{C_SQH,-C_SQH},{C_S3,-C_S1},
                          {0.f,-1.f},{-C_S3,-C_S1},{-C_SQH,-C_SQH},{-C_S1,-C_S3}};
    const float2 W16[4] = {{1.f,0.f},{C_SQH,-C_SQH},{0.f,-1.f},{-C_SQH,-C_SQH}};
    float2 a, b;
    #pragma unroll
    for (int j = 0; j < 8; ++j) {
        a=x[j]; b=x[j+8]; x[j]=cadd(a,b); x[j+8]=cmul(csub(a,b), W8[j]);
    }
    #pragma unroll
    for (int h = 0; h < 16; h += 8)
        #pragma unroll
        for (int j = 0; j < 4; ++j) {
            a=x[h+j]; b=x[h+j+4]; x[h+j]=cadd(a,b); x[h+j+4]=cmul(csub(a,b), W16[j]);
        }
    #pragma unroll
    for (int h = 0; h < 16; h += 4) {
        a=x[h];   b=x[h+2]; x[h]  =cadd(a,b); x[h+2]=csub(a,b);
        a=x[h+1]; b=x[h+3]; x[h+1]=cadd(a,b); x[h+3]=mul_negi(csub(a,b));
    }
    #pragma unroll
    for (int h = 0; h < 16; h += 2) {
        a=x[h]; b=x[h+1]; x[h]=cadd(a,b); x[h+1]=csub(a,b);
    }
}
static __device__ __forceinline__ void r16_core_inv(float2* x) {
    const float2 W16c[4] = {{1.f,0.f},{C_SQH,C_SQH},{0.f,1.f},{-C_SQH,C_SQH}};
    const float2 W8c[8]  = {{1.f,0.f},{C_S1,C_S3},{C_SQH,C_SQH},{C_S3,C_S1},
                            {0.f,1.f},{-C_S3,C_S1},{-C_SQH,C_SQH},{-C_S1,C_S3}};
    float2 a, bw;
    #pragma unroll
    for (int h = 0; h < 16; h += 2) {
        a=x[h]; bw=x[h+1]; x[h]=cadd(a,bw); x[h+1]=csub(a,bw);
    }
    #pragma unroll
    for (int h = 0; h < 16; h += 4) {
        a=x[h];   bw=x[h+2];        x[h]  =cadd(a,bw);  x[h+2]=csub(a,bw);
        a=x[h+1]; bw=mul_i(x[h+3]); x[h+1]=cadd(a,bw);  x[h+3]=csub(a,bw);
    }
    #pragma unroll
    for (int h = 0; h < 16; h += 8)
        #pragma unroll
        for (int j = 0; j < 4; ++j) {
            a=x[h+j]; bw=cmul(x[h+j+4], W16c[j]);
            x[h+j]=cadd(a,bw); x[h+j+4]=csub(a,bw);
        }
    #pragma unroll
    for (int j = 0; j < 8; ++j) {
        a=x[j]; bw=cmul(x[j+8], W8c[j]);
        x[j]=cadd(a,bw); x[j+8]=csub(a,bw);
    }
}

// ---------------------------------------------------------------------------
// radix-8 pass (smem<->smem): DIF halves {64,32,16} / DIT halves {16,32,64}
// elements e = off + 16*j; lanes carry transform index t (conflict-free)
// ---------------------------------------------------------------------------
template<bool ROW>
static __device__ void pass_r8_fwd(float2* tile, const float2* tw) {
    #pragma unroll
    for (int k = 0; k < 2; ++k) {
        int q = threadIdx.x + k * NT;
        int t = q & 127, off = q >> 7;
        int base = ROW ? t * PITCH + off : off * PITCH + t;
        int str  = ROW ? 16 : 16 * PITCH;
        float2 x[8];
        #pragma unroll
        for (int j = 0; j < 8; ++j) x[j] = tile[base + j * str];
        float2 w1 = tw[off], w2 = tw[2*off], w4 = tw[4*off];
        float2 w1c1 = cmul(w1, make_float2(C_SQH, -C_SQH));
        float2 w1c2 = mul_negi(w1);
        float2 w1c3 = cmul(w1, make_float2(-C_SQH, -C_SQH));
        float2 a, b;
        a=x[0]; b=x[4]; x[0]=cadd(a,b); x[4]=cmul(csub(a,b), w1);
        a=x[1]; b=x[5]; x[1]=cadd(a,b); x[5]=cmul(csub(a,b), w1c1);
        a=x[2]; b=x[6]; x[2]=cadd(a,b); x[6]=cmul(csub(a,b), w1c2);
        a=x[3]; b=x[7]; x[3]=cadd(a,b); x[7]=cmul(csub(a,b), w1c3);
        float2 w2n = mul_negi(w2);
        a=x[0]; b=x[2]; x[0]=cadd(a,b); x[2]=cmul(csub(a,b), w2);
        a=x[1]; b=x[3]; x[1]=cadd(a,b); x[3]=cmul(csub(a,b), w2n);
        a=x[4]; b=x[6]; x[4]=cadd(a,b); x[6]=cmul(csub(a,b), w2);
        a=x[5]; b=x[7]; x[5]=cadd(a,b); x[7]=cmul(csub(a,b), w2n);
        #pragma unroll
        for (int p = 0; p < 4; ++p) {
            a=x[2*p]; b=x[2*p+1];
            x[2*p]=cadd(a,b); x[2*p+1]=cmul(csub(a,b), w4);
        }
        #pragma unroll
        for (int j = 0; j < 8; ++j) tile[base + j * str] = x[j];
    }
}

// EPI: 0 store complex; 1 accumulate |y| only; 2 store (|y|*scale,0) + accumulate
template<bool ROW, int EPI>
static __device__ float pass_r8_inv(float2* tile, const float2* tw, float scale) {
    float acc = 0.f;
    #pragma unroll
    for (int k = 0; k < 2; ++k) {
        int q = threadIdx.x + k * NT;
        int t = q & 127, off = q >> 7;
        int base = ROW ? t * PITCH + off : off * PITCH + t;
        int str  = ROW ? 16 : 16 * PITCH;
        float2 x[8];
        #pragma unroll
        for (int j = 0; j < 8; ++j) x[j] = tile[base + j * str];
        float2 w1c = cconj(tw[off]), w2c = cconj(tw[2*off]), w4c = cconj(tw[4*off]);
        float2 a, bw;
        #pragma unroll
        for (int p = 0; p < 4; ++p) {
            a=x[2*p]; bw=cmul(x[2*p+1], w4c);
            x[2*p]=cadd(a,bw); x[2*p+1]=csub(a,bw);
        }
        float2 w2ci = mul_i(w2c);
        a=x[0]; bw=cmul(x[2], w2c ); x[0]=cadd(a,bw); x[2]=csub(a,bw);
        a=x[1]; bw=cmul(x[3], w2ci); x[1]=cadd(a,bw); x[3]=csub(a,bw);
        a=x[4]; bw=cmul(x[6], w2c ); x[4]=cadd(a,bw); x[6]=csub(a,bw);
        a=x[5]; bw=cmul(x[7], w2ci); x[5]=cadd(a,bw); x[7]=csub(a,bw);
        float2 u0 = w1c;
        float2 u1 = cmul(w1c, make_float2(C_SQH, C_SQH));
        float2 u2 = mul_i(w1c);
        float2 u3 = cmul(w1c, make_float2(-C_SQH, C_SQH));
        a=x[0]; bw=cmul(x[4], u0); x[0]=cadd(a,bw); x[4]=csub(a,bw);
        a=x[1]; bw=cmul(x[5], u1); x[1]=cadd(a,bw); x[5]=csub(a,bw);
        a=x[2]; bw=cmul(x[6], u2); x[2]=cadd(a,bw); x[6]=csub(a,bw);
        a=x[3]; bw=cmul(x[7], u3); x[3]=cadd(a,bw); x[7]=csub(a,bw);
        if (EPI == 0) {
            #pragma unroll
            for (int j = 0; j < 8; ++j) tile[base + j * str] = x[j];
        } else {
            #pragma unroll
            for (int j = 0; j < 8; ++j) {
                float m = sqrtf(x[j].x * x[j].x + x[j].y * x[j].y);
                if (EPI == 2) {
                    m *= scale;
                    tile[base + j * str] = make_float2(m, 0.f);
                }
                acc += m;
            }
        }
    }
    return acc;
}

// ---------------------------------------------------------------------------
// r16 passes (1024 items = 128 transforms x 8 groups; exactly 1 per thread)
// ---------------------------------------------------------------------------
// inverse entry, column axis, fused with coalesced gmem read + PSI product:
// thread (t,g) reads elements r = 16g+j of column t; lanes span consecutive t
// -> each load instruction is a 256B coalesced transaction.
static __device__ void r16_col_inv_from_gmem(float2* tile,
                                             const float2* __restrict__ uh,
                                             const float*  __restrict__ ps) {
    int q = threadIdx.x;
    int t = q & 127, g = q >> 7;
    float2 x[16];
    #pragma unroll
    for (int j = 0; j < 16; ++j) {
        int e = (16 * g + j) * NN + t;
        float2 v = uh[e];
        float p = ps[e];
        x[j] = make_float2(v.x * p, v.y * p);
    }
    r16_core_inv(x);
    int base = (16 * g) * PITCH + t;
    #pragma unroll
    for (int j = 0; j < 16; ++j) tile[base + j * PITCH] = x[j];
}
static __device__ void r16_row_inv(float2* tile) {
    int q = threadIdx.x;
    int t = q & 127, g = q >> 7;
    int base = t * PITCH + 16 * g;
    float2 x[16];
    #pragma unroll
    for (int j = 0; j < 16; ++j) x[j] = tile[base + j];
    r16_core_inv(x);
    #pragma unroll
    for (int j = 0; j < 16; ++j) tile[base + j] = x[j];
}
static __device__ void r16_row_fwd(float2* tile) {
    int q = threadIdx.x;
    int t = q & 127, g = q >> 7;
    int base = t * PITCH + 16 * g;
    float2 x[16];
    #pragma unroll
    for (int j = 0; j < 16; ++j) x[j] = tile[base + j];
    r16_core_fwd(x);
    #pragma unroll
    for (int j = 0; j < 16; ++j) tile[base + j] = x[j];
}
// forward exit: r16 col core, coalesced gmem write (lanes -> consecutive t)
static __device__ void r16_col_fwd_to_gmem(float2* tile, float2* __restrict__ dst) {
    int q = threadIdx.x;
    int t = q & 127, g = q >> 7;
    int base = (16 * g) * PITCH + t;
    float2 x[16];
    #pragma unroll
    for (int j = 0; j < 16; ++j) x[j] = tile[base + j * PITCH];
    r16_core_fwd(x);
    #pragma unroll
    for (int j = 0; j < 16; ++j) dst[(16 * g + j) * NN + t] = x[j];
}

// ---------------------------------------------------------------------------
// K0: PSI in bit-reversed 2D order
// ---------------------------------------------------------------------------
static __device__ __forceinline__ float freqval(int i) {
    return (float)((i < 64) ? i : i - 128) * (6.283185307179586476925287e0f / 128.0f);
}
__global__ void k_psi() {
    int j = blockIdx.x >> 2, l = blockIdx.x & 3;
    float k0  = 2.356194490192345f / (float)(1 << j);
    float sg  = 0.8f * (float)(1 << j);
    float s2  = sg * sg;
    float th  = 0.7853981633974483f * (float)l;
    float k0x = k0 * cosf(th), k0y = k0 * sinf(th);
    float beta = expf(-0.5f * s2 * k0 * k0);
    float* dst = g_psi + (j * 4 + l) * NPIX;
    for (int e = threadIdx.x; e < NPIX; e += blockDim.x) {
        int r = e >> 7, c = e & 127;
        float kx = freqval(brev7(r));
        float ky = freqval(brev7(c));
        float dx = kx - k0x, dy = ky - k0y;
        float g1 = expf(-0.5f * s2 * (dx * dx + dy * dy));
        float g0 = expf(-0.5f * s2 * (kx * kx + ky * ky));
        dst[e] = g1 - beta * g0;
    }
}

// ---------------------------------------------------------------------------
// K1: I_hat = fft2(image) + s0.  grid = 64
// ---------------------------------------------------------------------------
__global__ __launch_bounds__(NT, 1)
void k_fft_image(const float* __restrict__ img) {
    Smem s = get_smem();
    init_tw(s.tw);
    const float* src = img + (size_t)blockIdx.x * NPIX;
    float acc = 0.f;
    #pragma unroll
    for (int k = 0; k < NPIX / NT; ++k) {
        int e = threadIdx.x + k * NT;
        float v = src[e];
        acc += v;
        s.tile[(e >> 7) * PITCH + (e & 127)] = make_float2(v, 0.f);
    }
    float tot = block_reduce32(acc, s.rbuf);   // syncs cover store->use
    if (threadIdx.x == 0) g_s0[blockIdx.x] = tot * (1.f / 16384.f);
    pass_r8_fwd<true>(s.tile, s.tw);  __syncthreads();
    r16_row_fwd(s.tile);              __syncthreads();
    pass_r8_fwd<false>(s.tile, s.tw); __syncthreads();
    r16_col_fwd_to_gmem(s.tile, g_Ihat + (size_t)blockIdx.x * NPIX);
}

// ---------------------------------------------------------------------------
// K2: u1 = |ifft2(I_hat*PSI)|/N^2; s1; u1_hat = fft2(u1) (j<3).  grid = 1024
// ---------------------------------------------------------------------------
__global__ __launch_bounds__(NT, 1)
void k_first() {
    Smem s = get_smem();
    init_tw(s.tw);
    int idx = blockIdx.x;
    int b = idx >> 4, j = (idx >> 2) & 3, l = idx & 3;
    const float2* ih = g_Ihat + (size_t)b * NPIX;
    const float*  ps = g_psi + (j * 4 + l) * NPIX;
    __syncthreads();                           // tw visible
    // inverse 2D, column axis first (entry fused with gmem product)
    r16_col_inv_from_gmem(s.tile, ih, ps);      __syncthreads();
    pass_r8_inv<false, 0>(s.tile, s.tw, 0.f);   __syncthreads();
    r16_row_inv(s.tile);                        __syncthreads();
    float acc = pass_r8_inv<true, 2>(s.tile, s.tw, 1.f / 16384.f);
    float tot = block_reduce32(acc, s.rbuf);    // syncs cover (u,0) stores
    if (threadIdx.x == 0) g_s1p[(b * 4 + j) * 4 + l] = tot;
    if (j < 3) {
        pass_r8_fwd<true>(s.tile, s.tw);  __syncthreads();
        r16_row_fwd(s.tile);              __syncthreads();
        pass_r8_fwd<false>(s.tile, s.tw); __syncthreads();
        r16_col_fwd_to_gmem(s.tile, g_U1hat + ((size_t)(b * 3 + j) * 4 + l) * NPIX);
    }
}

// ---------------------------------------------------------------------------
// K3: s2 partial = sum |ifft2(u1_hat * PSI_{j2,l2})|.  grid = 6144
// ---------------------------------------------------------------------------
__global__ __launch_bounds__(NT, 1)
void k_second() {
    Smem s = get_smem();
    init_tw(s.tw);
    int idx = blockIdx.x;
    int b = idx / 96;
    int r0 = idx - b * 96;
    int p = r0 >> 4, l1 = (r0 >> 2) & 3, l2 = r0 & 3;
    int j1 = c_j1[p], j2 = c_j2[p];
    const float2* uh = g_U1hat + ((size_t)(b * 3 + j1) * 4 + l1) * NPIX;
    const float*  ps = g_psi + (j2 * 4 + l2) * NPIX;
    __syncthreads();                           // tw visible
    r16_col_inv_from_gmem(s.tile, uh, ps);      __syncthreads();
    pass_r8_inv<false, 0>(s.tile, s.tw, 0.f);   __syncthreads();
    r16_row_inv(s.tile);                        __syncthreads();
    float acc = pass_r8_inv<true, 1>(s.tile, s.tw, 0.f);
    float tot = block_reduce32(acc, s.rbuf);
    if (threadIdx.x == 0) g_s2p[(b * 6 + p) * 16 + (l1 * 4 + l2)] = tot * (1.f / 16384.f);
}

// ---------------------------------------------------------------------------
// K4: finalize + MLP
// ---------------------------------------------------------------------------
__global__ void k_final(const float* __restrict__ fc1w, const float* __restrict__ fc1b,
                        const float* __restrict__ fc2w, const float* __restrict__ fc2b,
                        float* __restrict__ out) {
    int b = threadIdx.x;
    if (b >= NB) return;
    float coeffs[11];
    coeffs[0] = g_s0[b];
    #pragma unroll
    for (int j = 0; j < 4; ++j) {
        float s = 0.f;
        #pragma unroll
        for (int l = 0; l < 4; ++l) s += g_s1p[(b * 4 + j) * 4 + l];
        coeffs[1 + j] = s * (1.f / 65536.f);
    }
    #pragma unroll
    for (int p = 0; p < 6; ++p) {
        float s = 0.f;
        #pragma unroll
        for (int i = 0; i < 16; ++i) s += g_s2p[(b * 6 + p) * 16 + i];
        coeffs[5 + p] = s * (1.f / (16.f * 16384.f));
    }
    float h[4];
    #pragma unroll
    for (int i = 0; i < 4; ++i) {
        float a = fc1b[i];
        #pragma unroll
        for (int k = 0; k < 11; ++k) a += coeffs[k] * fc1w[i * 11 + k];
        h[i] = fmaxf(a, 0.f);
    }
    #pragma unroll
    for (int o = 0; o < 10; ++o) {
        float a = fc2b[o];
        #pragma unroll
        for (int i = 0; i < 4; ++i) a += h[i] * fc2w[o * 4 + i];
        out[b * 10 + o] = 1.f / (1.f + expf(-a));
    }
}

// ---------------------------------------------------------------------------
extern "C" void kernel_launch(void* const* d_in, const int* in_sizes, int n_in,
                              void* d_out, int out_size) {
    (void)in_sizes; (void)n_in; (void)out_size;
    const float* img  = (const float*)d_in[0];
    const float* fc1w = (const float*)d_in[1];
    const float* fc1b = (const float*)d_in[2];
    const float* fc2w = (const float*)d_in[3];
    const float* fc2b = (const float*)d_in[4];
    float* out = (float*)d_out;

    const int smem_sz = NN * PITCH * (int)sizeof(float2)
                      + 64 * (int)sizeof(float2) + 32 * (int)sizeof(float);
    cudaFuncSetAttribute(k_fft_image, cudaFuncAttributeMaxDynamicSharedMemorySize, smem_sz);
    cudaFuncSetAttribute(k_first,     cudaFuncAttributeMaxDynamicSharedMemorySize, smem_sz);
    cudaFuncSetAttribute(k_second,    cudaFuncAttributeMaxDynamicSharedMemorySize, smem_sz);

    k_psi<<<16, 256>>>();
    k_fft_image<<<NB, NT, smem_sz>>>(img);
    k_first<<<NB * 16, NT, smem_sz>>>();
    k_second<<<NB * 96, NT, smem_sz>>>();
    k_final<<<1, 64>>>(fc1w, fc1b, fc2w, fc2b, out);
}